// round 1
// baseline (speedup 1.0000x reference)
#include <cuda_runtime.h>
#include <math.h>

#define BATCH 4
#define SEQ   2048
#define DIM   512
#define NHEAD 8
#define DHEAD 64
#define MROWS (BATCH*SEQ)      // 8192
#define HB    (NHEAD*BATCH)    // 32

#define NEG_INF_F (-4294967295.0f)   // -(2^32 - 1)
#define LN_EPS 1e-8f

// Scratch (no allocation allowed in kernel_launch)
static __device__ float g_Q[MROWS*DIM];
static __device__ float g_K[MROWS*DIM];
static __device__ float g_V[MROWS*DIM];
static __device__ float g_O[MROWS*DIM];
static __device__ float g_kmask[MROWS];
static __device__ float g_qmask[MROWS];

// ---------------------------------------------------------------------------
// Masks: sign(abs(rowsum)) for keys and queries. Warp per row.
// ---------------------------------------------------------------------------
__global__ void __launch_bounds__(256) mask_kernel(const float* __restrict__ keys,
                                                   const float* __restrict__ queries)
{
    int warp = threadIdx.x >> 5;
    int lane = threadIdx.x & 31;
    int row  = blockIdx.x * 8 + warp;
    if (row >= MROWS) return;
    float sk = 0.f, sq = 0.f;
    const float* kr = keys    + (size_t)row * DIM;
    const float* qr = queries + (size_t)row * DIM;
    for (int c = lane; c < DIM; c += 32) { sk += kr[c]; sq += qr[c]; }
    #pragma unroll
    for (int o = 16; o > 0; o >>= 1) {
        sk += __shfl_xor_sync(0xffffffffu, sk, o);
        sq += __shfl_xor_sync(0xffffffffu, sq, o);
    }
    if (lane == 0) {
        g_kmask[row] = (sk != 0.0f) ? 1.0f : 0.0f;
        g_qmask[row] = (sq != 0.0f) ? 1.0f : 0.0f;
    }
}

// ---------------------------------------------------------------------------
// Projection GEMM: C[M,512] = relu(A[M,512] @ W[512,512] + bias), 128x128x8 tile
// ---------------------------------------------------------------------------
__global__ void __launch_bounds__(256) proj_gemm(const float* __restrict__ A,
                                                 const float* __restrict__ W,
                                                 const float* __restrict__ bias,
                                                 float* __restrict__ C)
{
    __shared__ float As[8][128];
    __shared__ float Bs[8][128];

    const int tid = threadIdx.x;
    const int tx  = tid & 15;
    const int ty  = tid >> 4;
    const int bm  = blockIdx.y * 128;
    const int bn  = blockIdx.x * 128;

    const int a_row = tid >> 1;          // 0..127
    const int a_col = (tid & 1) * 4;     // 0 or 4
    const int b_row = tid >> 5;          // 0..7
    const int b_col = (tid & 31) * 4;    // 0..124

    float acc[8][8];
    #pragma unroll
    for (int i = 0; i < 8; i++)
        #pragma unroll
        for (int j = 0; j < 8; j++) acc[i][j] = 0.f;

    for (int k0 = 0; k0 < DIM; k0 += 8) {
        float4 av = *(const float4*)&A[(size_t)(bm + a_row) * DIM + k0 + a_col];
        As[a_col + 0][a_row] = av.x;
        As[a_col + 1][a_row] = av.y;
        As[a_col + 2][a_row] = av.z;
        As[a_col + 3][a_row] = av.w;
        float4 bv = *(const float4*)&W[(size_t)(k0 + b_row) * DIM + bn + b_col];
        *(float4*)&Bs[b_row][b_col] = bv;
        __syncthreads();

        #pragma unroll
        for (int kk = 0; kk < 8; kk++) {
            float4 a0 = *(const float4*)&As[kk][ty * 4];
            float4 a1 = *(const float4*)&As[kk][64 + ty * 4];
            float4 b0 = *(const float4*)&Bs[kk][tx * 4];
            float4 b1 = *(const float4*)&Bs[kk][64 + tx * 4];
            float ar[8] = {a0.x, a0.y, a0.z, a0.w, a1.x, a1.y, a1.z, a1.w};
            float br[8] = {b0.x, b0.y, b0.z, b0.w, b1.x, b1.y, b1.z, b1.w};
            #pragma unroll
            for (int i = 0; i < 8; i++)
                #pragma unroll
                for (int j = 0; j < 8; j++) acc[i][j] += ar[i] * br[j];
        }
        __syncthreads();
    }

    // epilogue: bias + relu
    float bsv[8];
    {
        float4 c0 = *(const float4*)&bias[bn + tx * 4];
        float4 c1 = *(const float4*)&bias[bn + 64 + tx * 4];
        bsv[0]=c0.x; bsv[1]=c0.y; bsv[2]=c0.z; bsv[3]=c0.w;
        bsv[4]=c1.x; bsv[5]=c1.y; bsv[6]=c1.z; bsv[7]=c1.w;
    }
    #pragma unroll
    for (int i2 = 0; i2 < 2; i2++) {
        #pragma unroll
        for (int ii = 0; ii < 4; ii++) {
            int row = bm + i2 * 64 + ty * 4 + ii;
            #pragma unroll
            for (int j2 = 0; j2 < 2; j2++) {
                float4 ov;
                float* o = (float*)&ov;
                #pragma unroll
                for (int jj = 0; jj < 4; jj++) {
                    float v = acc[i2 * 4 + ii][j2 * 4 + jj] + bsv[j2 * 4 + jj];
                    o[jj] = fmaxf(v, 0.0f);
                }
                *(float4*)&C[(size_t)row * DIM + bn + j2 * 64 + tx * 4] = ov;
            }
        }
    }
}

// ---------------------------------------------------------------------------
// Attention: flash-style. CTA = (q-tile 64, head*batch). 256 thr = 16x16 of 4x4.
// smem: Qt [64d][68] (d-major), Xs = Kt/Pt union [64][68], Vs [64key][68]
// ---------------------------------------------------------------------------
#define ATT_STRIDE 68
#define ATT_SMEM_BYTES (3 * 64 * ATT_STRIDE * 4)

__global__ void __launch_bounds__(256) attn_kernel(float* __restrict__ Og)
{
    extern __shared__ float sm[];
    float* Qt = sm;                      // Qt[d*68 + q]
    float* Xs = sm + 64 * ATT_STRIDE;    // Kt[d*68 + key]  then  Pt[key*68 + q]
    float* Vs = sm + 2 * 64 * ATT_STRIDE;// Vs[key*68 + d]

    const int tid  = threadIdx.x;
    const int tx   = tid & 15;
    const int ty   = tid >> 4;
    const int hb   = blockIdx.y;
    const int head = hb >> 2;            // B = 4
    const int b    = hb & 3;
    const int qt0  = blockIdx.x * 64;

    const size_t base = (size_t)b * SEQ * DIM + head * DHEAD;

    // load Q tile transposed (d-major)
    for (int idx = tid; idx < 64 * 64; idx += 256) {
        int q = idx >> 6, d = idx & 63;
        Qt[d * ATT_STRIDE + q] = g_Q[base + (size_t)(qt0 + q) * DIM + d];
    }

    float m[4], l[4], o[4][4];
    #pragma unroll
    for (int i = 0; i < 4; i++) {
        m[i] = -INFINITY; l[i] = 0.f;
        #pragma unroll
        for (int j = 0; j < 4; j++) o[i][j] = 0.f;
    }

    for (int kt = 0; kt < SEQ / 64; kt++) {
        const int k0 = kt * 64;
        __syncthreads();   // prev GEMM2 done with Xs/Vs
        for (int idx = tid; idx < 64 * 64; idx += 256) {
            int key = idx >> 6, d = idx & 63;
            float kvv = g_K[base + (size_t)(k0 + key) * DIM + d];
            float vvv = g_V[base + (size_t)(k0 + key) * DIM + d];
            Xs[d * ATT_STRIDE + key] = kvv;   // K transposed
            Vs[key * ATT_STRIDE + d] = vvv;
        }
        float km4[4];
        #pragma unroll
        for (int j = 0; j < 4; j++)
            km4[j] = g_kmask[b * SEQ + k0 + tx * 4 + j];
        __syncthreads();

        // GEMM1: S = Q K^T
        float s[4][4];
        #pragma unroll
        for (int i = 0; i < 4; i++)
            #pragma unroll
            for (int j = 0; j < 4; j++) s[i][j] = 0.f;

        #pragma unroll 8
        for (int d = 0; d < 64; d++) {
            float4 qv = *(const float4*)&Qt[d * ATT_STRIDE + ty * 4];
            float4 kv = *(const float4*)&Xs[d * ATT_STRIDE + tx * 4];
            float qa[4] = {qv.x, qv.y, qv.z, qv.w};
            float ka[4] = {kv.x, kv.y, kv.z, kv.w};
            #pragma unroll
            for (int i = 0; i < 4; i++)
                #pragma unroll
                for (int j = 0; j < 4; j++) s[i][j] += qa[i] * ka[j];
        }

        // scale + key mask + online softmax
        #pragma unroll
        for (int i = 0; i < 4; i++)
            #pragma unroll
            for (int j = 0; j < 4; j++) {
                float v = s[i][j] * 0.125f;             // 1/sqrt(64)
                s[i][j] = (km4[j] == 0.0f) ? NEG_INF_F : v;
            }

        #pragma unroll
        for (int i = 0; i < 4; i++) {
            float mt = fmaxf(fmaxf(s[i][0], s[i][1]), fmaxf(s[i][2], s[i][3]));
            #pragma unroll
            for (int sh = 1; sh < 16; sh <<= 1)
                mt = fmaxf(mt, __shfl_xor_sync(0xffffffffu, mt, sh));
            float mn = fmaxf(m[i], mt);
            float al = __expf(m[i] - mn);
            float rs = 0.f;
            #pragma unroll
            for (int j = 0; j < 4; j++) {
                float p = __expf(s[i][j] - mn);
                s[i][j] = p;
                rs += p;
            }
            #pragma unroll
            for (int sh = 1; sh < 16; sh <<= 1)
                rs += __shfl_xor_sync(0xffffffffu, rs, sh);
            l[i] = l[i] * al + rs;
            m[i] = mn;
            #pragma unroll
            for (int j = 0; j < 4; j++) o[i][j] *= al;
        }

        __syncthreads();   // done reading Xs as K
        // write P transposed: Pt[key][q]
        #pragma unroll
        for (int j = 0; j < 4; j++) {
            float4 pv = make_float4(s[0][j], s[1][j], s[2][j], s[3][j]);
            *(float4*)&Xs[(tx * 4 + j) * ATT_STRIDE + ty * 4] = pv;
        }
        __syncthreads();

        // GEMM2: O += P V
        #pragma unroll 8
        for (int k = 0; k < 64; k++) {
            float4 pv = *(const float4*)&Xs[k * ATT_STRIDE + ty * 4];
            float4 vv = *(const float4*)&Vs[k * ATT_STRIDE + tx * 4];
            float pa[4] = {pv.x, pv.y, pv.z, pv.w};
            float va[4] = {vv.x, vv.y, vv.z, vv.w};
            #pragma unroll
            for (int i = 0; i < 4; i++)
                #pragma unroll
                for (int j = 0; j < 4; j++) o[i][j] += pa[i] * va[j];
        }
    }

    // epilogue: normalize by l, apply query mask, write merged-head layout
    #pragma unroll
    for (int i = 0; i < 4; i++) {
        int q = qt0 + ty * 4 + i;
        float qmv = g_qmask[b * SEQ + q];
        float inv = qmv / l[i];
        float4 ov = make_float4(o[i][0] * inv, o[i][1] * inv, o[i][2] * inv, o[i][3] * inv);
        *(float4*)&Og[base + (size_t)q * DIM + tx * 4] = ov;
    }
}

// ---------------------------------------------------------------------------
// Residual + LayerNorm (ddof=1, eps added to std). Block per row, 128 threads.
// ---------------------------------------------------------------------------
__device__ __forceinline__ float block_sum_128(float v, float* red)
{
    #pragma unroll
    for (int o = 16; o > 0; o >>= 1) v += __shfl_xor_sync(0xffffffffu, v, o);
    int lane = threadIdx.x & 31, w = threadIdx.x >> 5;
    if (lane == 0) red[w] = v;
    __syncthreads();
    float t = red[0] + red[1] + red[2] + red[3];
    __syncthreads();
    return t;
}

__global__ void __launch_bounds__(128) ln_kernel(const float* __restrict__ queries,
                                                 const float* __restrict__ gamma,
                                                 const float* __restrict__ beta,
                                                 float* __restrict__ out)
{
    __shared__ float red[4];
    const int row = blockIdx.x;
    const int tid = threadIdx.x;
    const size_t rb = (size_t)row * DIM;

    float x[4];
    #pragma unroll
    for (int u = 0; u < 4; u++) {
        int c = tid + u * 128;
        x[u] = g_O[rb + c] + queries[rb + c];
    }
    float s = x[0] + x[1] + x[2] + x[3];
    float total = block_sum_128(s, red);
    float mean = total * (1.0f / DIM);

    float ss = 0.f;
    #pragma unroll
    for (int u = 0; u < 4; u++) { float d = x[u] - mean; ss += d * d; }
    float sstot = block_sum_128(ss, red);
    float var = sstot * (1.0f / (DIM - 1));
    float rden = 1.0f / (sqrtf(var) + LN_EPS);

    #pragma unroll
    for (int u = 0; u < 4; u++) {
        int c = tid + u * 128;
        out[rb + c] = gamma[c] * (x[u] - mean) * rden + beta[c];
    }
}

// ---------------------------------------------------------------------------
extern "C" void kernel_launch(void* const* d_in, const int* in_sizes, int n_in,
                              void* d_out, int out_size)
{
    const float* queries = (const float*)d_in[0];
    const float* keys    = (const float*)d_in[1];
    const float* values  = (const float*)d_in[2];
    const float* Wq      = (const float*)d_in[3];
    const float* bq      = (const float*)d_in[4];
    const float* Wk      = (const float*)d_in[5];
    const float* bk      = (const float*)d_in[6];
    const float* Wv      = (const float*)d_in[7];
    const float* bv      = (const float*)d_in[8];
    const float* gamma   = (const float*)d_in[9];
    const float* beta    = (const float*)d_in[10];
    float* out = (float*)d_out;

    float *pQ, *pK, *pV, *pO;
    cudaGetSymbolAddress((void**)&pQ, g_Q);
    cudaGetSymbolAddress((void**)&pK, g_K);
    cudaGetSymbolAddress((void**)&pV, g_V);
    cudaGetSymbolAddress((void**)&pO, g_O);

    cudaFuncSetAttribute(attn_kernel, cudaFuncAttributeMaxDynamicSharedMemorySize,
                         ATT_SMEM_BYTES);

    // 1. masks
    mask_kernel<<<MROWS / 8, 256>>>(keys, queries);

    // 2. projections
    dim3 pgrid(DIM / 128, MROWS / 128);
    proj_gemm<<<pgrid, 256>>>(queries, Wq, bq, pQ);
    proj_gemm<<<pgrid, 256>>>(keys,    Wk, bk, pK);
    proj_gemm<<<pgrid, 256>>>(values,  Wv, bv, pV);

    // 3. attention
    dim3 agrid(SEQ / 64, HB);
    attn_kernel<<<agrid, 256, ATT_SMEM_BYTES>>>(pO);

    // 4. residual + layernorm
    ln_kernel<<<MROWS, 128>>>(queries, gamma, beta, out);
}